// round 17
// baseline (speedup 1.0000x reference)
#include <cuda_runtime.h>
#include <math.h>

// ----- problem dims -----
#define B_    32
#define T_    100
#define NN_   32
#define F_    8
#define D_    256
#define LH    512
#define G4    2048      // 4*LH
#define ROWS  3200      // B_*T_  (row = t*32 + b)
#define NBLK  64        // persistent LSTM grid
#define JPB   8         // hidden units per block
#define PAD   34        // pacc row stride (floats) — MUST be even (float2 stores)

typedef unsigned long long ull;
typedef unsigned int uint;

// ----- device scratch -----
__device__ float d_G   [ROWS * D_];
__device__ float d_Pk  [4 * G4 * D_]; // split-K partials (folds)
__device__ float d_F1  [G4 * D_];     // w_ih @ Wop
__device__ float d_Wbig[G4 * D_];     // w_ih @ Wop @ Wv
__device__ float d_batt[D_];          // Wop@bv + bop
__device__ float d_bihh[G4];          // w_ih@batt + b_ih + b_hh
__device__ float d_XT  [G4 * ROWS];   // X^T: [gate*512+j][t*32+b]
__device__ float d_hbuf[2][B_ * LH];  // q-grouped: (j>>2)*128 + b*4 + (j&3)
__device__ float d_LT  [LH * ROWS];   // L^T: [j][t*32+b]
__device__ float d_H1  [ROWS * D_];
__device__ int   d_bar;               // central barrier counter

__device__ __forceinline__ uint f2tf32(float x) {
    uint r;
    asm("cvt.rna.tf32.f32 %0, %1;" : "=r"(r) : "f"(x));
    return r;
}
__device__ __forceinline__ float tanh_fast(float x) {
    float ax = fabsf(x);
    float e  = __expf(-2.0f * ax);
    float t  = __fdividef(1.0f - e, 1.0f + e);
    return copysignf(t, x);
}
__device__ __forceinline__ float sigm(float x) {
    return 1.0f / (1.0f + __expf(-x));
}
__device__ __forceinline__ void red_release_add(int* p, int v) {
    asm volatile("red.release.gpu.global.add.s32 [%0], %1;" :: "l"(p), "r"(v) : "memory");
}
__device__ __forceinline__ int ld_acq(const int* p) {
    int v;
    asm volatile("ld.acquire.gpu.global.b32 %0, [%1];" : "=r"(v) : "l"(p) : "memory");
    return v;
}

// ======================================================================
// k_init: G = relu(mean_n(traj) @ gcn_w + gcn_b); also zero h[0], bar
// ======================================================================
__global__ void k_init(const float* __restrict__ traj,
                       const float* __restrict__ gw,
                       const float* __restrict__ gb) {
    int row = blockIdx.x;
    int t = row >> 5, b = row & 31;
    __shared__ float s[NN_ * F_];
    __shared__ float m[F_];
    int tid = threadIdx.x;

    if (row < 64) d_hbuf[0][row * 256 + tid] = 0.0f;
    if (row == 0 && tid == 0) d_bar = 0;

    const float* p = traj + (size_t)((b * T_ + t) * NN_) * F_;
    s[tid] = p[tid];
    __syncthreads();
    if (tid < F_) {
        float acc = 0.0f;
        #pragma unroll
        for (int n = 0; n < NN_; n++) acc += s[n * F_ + tid];
        m[tid] = acc * (1.0f / 32.0f);
    }
    __syncthreads();
    float acc = gb[tid];
    #pragma unroll
    for (int f = 0; f < F_; f++) acc += m[f] * gw[f * D_ + tid];
    d_G[(size_t)row * D_ + tid] = fmaxf(acc, 0.0f);
}

// ======================================================================
// GEMV (warp-per-row)
// ======================================================================
__global__ void k_gemv(const float* __restrict__ W, int K,
                       const float* __restrict__ x,
                       const float* __restrict__ add1,
                       const float* __restrict__ add2,
                       float* __restrict__ out, int M) {
    int gw   = (blockIdx.x * blockDim.x + threadIdx.x) >> 5;
    int lane = threadIdx.x & 31;
    if (gw >= M) return;
    float s = 0.0f;
    for (int k = lane; k < K; k += 32)
        s += W[(size_t)gw * K + k] * x[k];
    #pragma unroll
    for (int off = 16; off > 0; off >>= 1)
        s += __shfl_xor_sync(0xffffffff, s, off);
    if (lane == 0) {
        float r = s + add1[gw];
        if (add2) r += add2[gw];
        out[gw] = r;
    }
}

// ======================================================================
// k_addn: C[i] = sum_{p<nparts} P[p*len4 + i]
// ======================================================================
__global__ void k_addn(const float* __restrict__ P, float* __restrict__ C,
                       int len4, int nparts) {
    int i = blockIdx.x * blockDim.x + threadIdx.x;
    if (i < len4) {
        float4 v = ((const float4*)P)[i];
        for (int p = 1; p < nparts; p++) {
            float4 a = ((const float4*)P)[(size_t)p * len4 + i];
            v.x += a.x; v.y += a.y; v.z += a.z; v.w += a.w;
        }
        ((float4*)C)[i] = v;
    }
}

// ======================================================================
// Scalar fp32 fold GEMM (proven): NN, split-K via blockIdx.z
// ======================================================================
__global__ void __launch_bounds__(256)
sgemm_fold(const float* __restrict__ A, const float* __restrict__ Bm,
           float* __restrict__ C, int M, int N, int K,
           int lda, int ldb, size_t kadvA, size_t kadvB) {
    __shared__ __align__(16) float As[16][64];
    __shared__ __align__(16) float Bs[16][128];

    int tid = threadIdx.x;
    int m0 = blockIdx.y * 64, n0 = blockIdx.x * 128;
    int tm = (tid >> 4) * 4, tn = (tid & 15) * 8;

    A  += blockIdx.z * kadvA;
    Bm += blockIdx.z * kadvB;
    C  += (size_t)blockIdx.z * M * N;

    float acc[4][8];
    #pragma unroll
    for (int i = 0; i < 4; i++)
        #pragma unroll
        for (int j = 0; j < 8; j++) acc[i][j] = 0.0f;

    for (int k0 = 0; k0 < K; k0 += 16) {
        {
            int r  = tid >> 2;
            int kq = (tid & 3) * 4;
            float4 va = *(const float4*)&A[(size_t)(m0 + r) * lda + k0 + kq];
            As[kq + 0][r] = va.x; As[kq + 1][r] = va.y;
            As[kq + 2][r] = va.z; As[kq + 3][r] = va.w;
        }
        #pragma unroll
        for (int i = 0; i < 2; i++) {
            int idx = tid + i * 256;
            int kk = idx >> 5;
            int c  = (idx & 31) * 4;
            float4 vb = *(const float4*)&Bm[(size_t)(k0 + kk) * ldb + n0 + c];
            *(float4*)&Bs[kk][c] = vb;
        }
        __syncthreads();
        #pragma unroll
        for (int kk = 0; kk < 16; kk++) {
            float a[4], b[8];
            *(float4*)&a[0] = *(const float4*)&As[kk][tm];
            *(float4*)&b[0] = *(const float4*)&Bs[kk][tn];
            *(float4*)&b[4] = *(const float4*)&Bs[kk][tn + 4];
            #pragma unroll
            for (int i = 0; i < 4; i++)
                #pragma unroll
                for (int j = 0; j < 8; j++)
                    acc[i][j] += a[i] * b[j];
        }
        __syncthreads();
    }

    #pragma unroll
    for (int i = 0; i < 4; i++) {
        float* crow = C + (size_t)(m0 + tm + i) * N;
        #pragma unroll
        for (int j = 0; j < 8; j += 4) {
            float4 v = make_float4(acc[i][j], acc[i][j+1], acc[i][j+2], acc[i][j+3]);
            *(float4*)&crow[n0 + tn + j] = v;
        }
    }
}

// ======================================================================
// TF32 GEMM template (proven R14).
// ======================================================================
template<int AKM, int BKM, int BMODE, int RELU, int PERM>
__global__ void __launch_bounds__(256)
tf32gemm(const float* __restrict__ A, const float* __restrict__ Bm,
         const float* __restrict__ bias, float* __restrict__ C,
         int M, int N, int K, int lda, int ldb) {
    constexpr int ASZ = AKM ? 32 * 136 : 128 * 36;
    constexpr int BSZ = BKM ? 32 * 136 : 128 * 36;
    __shared__ __align__(16) uint As[ASZ];
    __shared__ __align__(16) uint Bs[BSZ];

    int tid = threadIdx.x, lane = tid & 31, wid = tid >> 5;
    int g = lane >> 2, t = lane & 3;
    int warp_m = wid >> 2, warp_n = wid & 3;
    int m0 = blockIdx.y * 128, n0 = blockIdx.x * 128;

    float c[4][4][4];
    #pragma unroll
    for (int i = 0; i < 4; i++)
        #pragma unroll
        for (int j = 0; j < 4; j++)
            #pragma unroll
            for (int e = 0; e < 4; e++) c[i][j][e] = 0.0f;

    for (int k0 = 0; k0 < K; k0 += 32) {
        #pragma unroll
        for (int i = 0; i < 4; i++) {
            int idx = tid + i * 256;
            if constexpr (AKM == 0) {
                int r  = idx >> 3;
                int kq = (idx & 7) * 4;
                float4 va = *(const float4*)&A[(size_t)(m0 + r) * lda + k0 + kq];
                uint4 w = make_uint4(f2tf32(va.x), f2tf32(va.y),
                                     f2tf32(va.z), f2tf32(va.w));
                *(uint4*)&As[r * 36 + kq] = w;
            } else {
                int kk = idx >> 5;
                int cc = (idx & 31) * 4;
                float4 va = *(const float4*)&A[(size_t)(k0 + kk) * lda + m0 + cc];
                uint4 w = make_uint4(f2tf32(va.x), f2tf32(va.y),
                                     f2tf32(va.z), f2tf32(va.w));
                *(uint4*)&As[kk * 136 + cc] = w;
            }
        }
        #pragma unroll
        for (int i = 0; i < 4; i++) {
            int idx = tid + i * 256;
            if constexpr (BKM == 0) {
                int r  = idx >> 3;
                int kq = (idx & 7) * 4;
                float4 vb = *(const float4*)&Bm[(size_t)(n0 + r) * ldb + k0 + kq];
                uint4 w = make_uint4(f2tf32(vb.x), f2tf32(vb.y),
                                     f2tf32(vb.z), f2tf32(vb.w));
                *(uint4*)&Bs[r * 36 + kq] = w;
            } else {
                int kk = idx >> 5;
                int cc = (idx & 31) * 4;
                float4 vb = *(const float4*)&Bm[(size_t)(k0 + kk) * ldb + n0 + cc];
                uint4 w = make_uint4(f2tf32(vb.x), f2tf32(vb.y),
                                     f2tf32(vb.z), f2tf32(vb.w));
                *(uint4*)&Bs[kk * 136 + cc] = w;
            }
        }
        __syncthreads();

        #pragma unroll
        for (int kb = 0; kb < 32; kb += 8) {
            uint bfr[4][2];
            #pragma unroll
            for (int nf = 0; nf < 4; nf++) {
                int n = warp_n * 32 + nf * 8 + g;
                if constexpr (BKM == 0) {
                    bfr[nf][0] = Bs[n * 36 + kb + t];
                    bfr[nf][1] = Bs[n * 36 + kb + t + 4];
                } else {
                    bfr[nf][0] = Bs[(kb + t) * 136 + n];
                    bfr[nf][1] = Bs[(kb + t + 4) * 136 + n];
                }
            }
            #pragma unroll
            for (int mf = 0; mf < 4; mf++) {
                int m = warp_m * 64 + mf * 16 + g;
                uint a0, a1, a2, a3;
                if constexpr (AKM == 0) {
                    a0 = As[m * 36 + kb + t];       a1 = As[(m + 8) * 36 + kb + t];
                    a2 = As[m * 36 + kb + t + 4];   a3 = As[(m + 8) * 36 + kb + t + 4];
                } else {
                    a0 = As[(kb + t) * 136 + m];     a1 = As[(kb + t) * 136 + m + 8];
                    a2 = As[(kb + t + 4) * 136 + m]; a3 = As[(kb + t + 4) * 136 + m + 8];
                }
                #pragma unroll
                for (int nf = 0; nf < 4; nf++) {
                    asm volatile(
                        "mma.sync.aligned.m16n8k8.row.col.f32.tf32.tf32.f32 "
                        "{%0,%1,%2,%3}, {%4,%5,%6,%7}, {%8,%9}, {%0,%1,%2,%3};"
                        : "+f"(c[mf][nf][0]), "+f"(c[mf][nf][1]),
                          "+f"(c[mf][nf][2]), "+f"(c[mf][nf][3])
                        : "r"(a0), "r"(a1), "r"(a2), "r"(a3),
                          "r"(bfr[nf][0]), "r"(bfr[nf][1]));
                }
            }
        }
        __syncthreads();
    }

    #pragma unroll
    for (int mf = 0; mf < 4; mf++) {
        int mg = m0 + warp_m * 64 + mf * 16 + g;
        float b0v = 0.0f, b1v = 0.0f;
        if constexpr (BMODE == 1) { b0v = bias[mg]; b1v = bias[mg + 8]; }
        size_t row0, row1;
        if constexpr (PERM) {
            row0 = (size_t)((mg & 31) * T_ + (mg >> 5));
            row1 = (size_t)(((mg + 8) & 31) * T_ + ((mg + 8) >> 5));
        } else {
            row0 = (size_t)mg; row1 = (size_t)(mg + 8);
        }
        #pragma unroll
        for (int nf = 0; nf < 4; nf++) {
            int ng = n0 + warp_n * 32 + nf * 8 + t * 2;
            float bnx = 0.0f, bny = 0.0f;
            if constexpr (BMODE == 2) {
                float2 bb = *(const float2*)&bias[ng];
                bnx = bb.x; bny = bb.y;
            }
            float2 v0 = make_float2(c[mf][nf][0] + b0v + bnx, c[mf][nf][1] + b0v + bny);
            float2 v1 = make_float2(c[mf][nf][2] + b1v + bnx, c[mf][nf][3] + b1v + bny);
            if constexpr (RELU) {
                v0.x = fmaxf(v0.x, 0.0f); v0.y = fmaxf(v0.y, 0.0f);
                v1.x = fmaxf(v1.x, 0.0f); v1.y = fmaxf(v1.y, 0.0f);
            }
            *(float2*)&C[row0 * N + ng] = v0;
            *(float2*)&C[row1 * N + ng] = v1;
        }
    }
}

// ======================================================================
// Persistent LSTM, tensor-core, 64 blocks x 256 threads.
// Block owns JPB=8 hidden units -> 32 gate rows (r = gate*8 + jj).
// Warp w covers K slice [w*64, w*64+64), computes 2 m16 tiles x 4 nf.
// hi-weights in registers (compensated); lo-weights in shared (static).
// h fragments read direct from global q-grouped hbuf (coalesced LDG.32).
// smem: wlo 64KB | pacc 8*32*34*4 | cs 1KB
// ======================================================================
#define SM_WLO   0
#define SM_PACC  (SM_WLO + 8 * 2 * 8 * 32 * 16)
#define SM_CS    (SM_PACC + 8 * 32 * PAD * 4)
#define SM_TOTAL (SM_CS + 256 * 4)

__global__ void __launch_bounds__(256, 1)
k_lstm(const float* __restrict__ whh) {
    extern __shared__ char smem[];
    float4* wlo4 = (float4*)(smem + SM_WLO);   // [(wrp*2+mt)*8+kc][lane]
    float*  pacc = (float*) (smem + SM_PACC);  // [(wrp*32+row)*PAD + col]
    float*  cs   = (float*) (smem + SM_CS);    // [tid] : (jj,b)

    int tid = threadIdx.x, lane = tid & 31, wrp = tid >> 5;
    int g = lane >> 2, t = lane & 3;
    int j0 = blockIdx.x * JPB;

    // ---- static A fragments: 2 m-tiles, rows r = mt*16 + (g | g+8) ----
    uint ahi[2][8][4];
    #pragma unroll
    for (int mt = 0; mt < 2; mt++) {
        int r0 = mt * 16 + g, r1 = mt * 16 + g + 8;
        int rr0 = (r0 >> 3) * LH + j0 + (r0 & 7);
        int rr1 = (r1 >> 3) * LH + j0 + (r1 & 7);
        #pragma unroll
        for (int kc = 0; kc < 8; kc++) {
            int kg = wrp * 64 + kc * 8 + t;
            float w00 = whh[(size_t)rr0 * LH + kg];
            float w10 = whh[(size_t)rr1 * LH + kg];
            float w01 = whh[(size_t)rr0 * LH + kg + 4];
            float w11 = whh[(size_t)rr1 * LH + kg + 4];
            ahi[mt][kc][0] = f2tf32(w00); ahi[mt][kc][1] = f2tf32(w10);
            ahi[mt][kc][2] = f2tf32(w01); ahi[mt][kc][3] = f2tf32(w11);
            uint4 lo;
            lo.x = f2tf32(w00 - __uint_as_float(ahi[mt][kc][0]));
            lo.y = f2tf32(w10 - __uint_as_float(ahi[mt][kc][1]));
            lo.z = f2tf32(w01 - __uint_as_float(ahi[mt][kc][2]));
            lo.w = f2tf32(w11 - __uint_as_float(ahi[mt][kc][3]));
            wlo4[((wrp * 2 + mt) * 8 + kc) * 32 + lane] = *(float4*)&lo;
        }
    }
    cs[tid] = 0.0f;
    __syncthreads();

    const int pjj = tid >> 5;          // pointwise: jj 0..7
    const int pb  = tid & 31;
    const size_t xbase = (size_t)(j0 + pjj) * ROWS + pb;
    const size_t gstr  = (size_t)LH * ROWS;
    // h write address for pointwise
    const int hw = (blockIdx.x * 2 + (pjj >> 2)) * 128 + pb * 4 + (pjj & 3);

    float xg[4];
    #pragma unroll
    for (int gg = 0; gg < 4; gg++)
        xg[gg] = __ldcg(&d_XT[xbase + gg * gstr]);

    const int hb0 = wrp * 16 * 128 + t;

    for (int tt = 0; tt < T_; tt++) {
        const float* hf = d_hbuf[tt & 1];

        float xn[4] = {0, 0, 0, 0};
        if (tt + 1 < T_) {
            size_t o = xbase + (tt + 1) * 32;
            #pragma unroll
            for (int gg = 0; gg < 4; gg++)
                xn[gg] = __ldcg(&d_XT[o + gg * gstr]);
        }

        float c[2][4][4];
        #pragma unroll
        for (int mt = 0; mt < 2; mt++)
            #pragma unroll
            for (int nf = 0; nf < 4; nf++)
                #pragma unroll
                for (int e = 0; e < 4; e++) c[mt][nf][e] = 0.0f;

        #pragma unroll
        for (int kc = 0; kc < 8; kc++) {
            int base0 = hb0 + 2 * kc * 128;
            int base1 = base0 + 128;
            uint bh[4][2];
            #pragma unroll
            for (int nf = 0; nf < 4; nf++) {
                int n4 = (nf * 8 + g) * 4;
                bh[nf][0] = f2tf32(__ldcg(&hf[base0 + n4]));
                bh[nf][1] = f2tf32(__ldcg(&hf[base1 + n4]));
            }
            #pragma unroll
            for (int mt = 0; mt < 2; mt++) {
                float4 lof = wlo4[((wrp * 2 + mt) * 8 + kc) * 32 + lane];
                uint4 lo = *(uint4*)&lof;
                #pragma unroll
                for (int nf = 0; nf < 4; nf++) {
                    asm volatile(
                        "mma.sync.aligned.m16n8k8.row.col.f32.tf32.tf32.f32 "
                        "{%0,%1,%2,%3}, {%4,%5,%6,%7}, {%8,%9}, {%0,%1,%2,%3};"
                        : "+f"(c[mt][nf][0]), "+f"(c[mt][nf][1]),
                          "+f"(c[mt][nf][2]), "+f"(c[mt][nf][3])
                        : "r"(ahi[mt][kc][0]), "r"(ahi[mt][kc][1]),
                          "r"(ahi[mt][kc][2]), "r"(ahi[mt][kc][3]),
                          "r"(bh[nf][0]), "r"(bh[nf][1]));
                    asm volatile(
                        "mma.sync.aligned.m16n8k8.row.col.f32.tf32.tf32.f32 "
                        "{%0,%1,%2,%3}, {%4,%5,%6,%7}, {%8,%9}, {%0,%1,%2,%3};"
                        : "+f"(c[mt][nf][0]), "+f"(c[mt][nf][1]),
                          "+f"(c[mt][nf][2]), "+f"(c[mt][nf][3])
                        : "r"(lo.x), "r"(lo.y), "r"(lo.z), "r"(lo.w),
                          "r"(bh[nf][0]), "r"(bh[nf][1]));
                }
            }
        }

        // D fragments -> pacc
        #pragma unroll
        for (int mt = 0; mt < 2; mt++) {
            int r0 = mt * 16 + g, r1 = mt * 16 + g + 8;
            #pragma unroll
            for (int nf = 0; nf < 4; nf++) {
                int col = nf * 8 + 2 * t;
                *(float2*)&pacc[(wrp * 32 + r0) * PAD + col] =
                    make_float2(c[mt][nf][0], c[mt][nf][1]);
                *(float2*)&pacc[(wrp * 32 + r1) * PAD + col] =
                    make_float2(c[mt][nf][2], c[mt][nf][3]);
            }
        }
        __syncthreads();

        // reduce + pointwise: all 256 threads, one (jj,b) each
        {
            float z[4];
            #pragma unroll
            for (int gg = 0; gg < 4; gg++) z[gg] = xg[gg];
            #pragma unroll
            for (int w = 0; w < 8; w++) {
                const float* pw = pacc + (size_t)(w * 32) * PAD + pb;
                #pragma unroll
                for (int gg = 0; gg < 4; gg++)
                    z[gg] += pw[(gg * 8 + pjj) * PAD];
            }
            float cp = cs[tid];
            float ig = sigm(z[0]), fg = sigm(z[1]);
            float gv = tanh_fast(z[2]), og = sigm(z[3]);
            float cn = fg * cp + ig * gv;
            float hn = og * tanh_fast(cn);
            cs[tid] = cn;
            d_hbuf[(tt + 1) & 1][hw] = hn;
            d_LT[(size_t)(j0 + pjj) * ROWS + tt * 32 + pb] = hn;
        }
        #pragma unroll
        for (int gg = 0; gg < 4; gg++) xg[gg] = xn[gg];

        __syncthreads();
        if (tid == 0) {
            red_release_add(&d_bar, 1);
            while (ld_acq(&d_bar) < NBLK * (tt + 1)) { }
        }
        __syncthreads();
    }
}

// ======================================================================
extern "C" void kernel_launch(void* const* d_in, const int* in_sizes, int n_in,
                              void* d_out, int out_size) {
    const float* traj      = (const float*)d_in[0];
    const float* gcn_w     = (const float*)d_in[1];
    const float* gcn_b     = (const float*)d_in[2];
    const float* in_proj_w = (const float*)d_in[3];
    const float* in_proj_b = (const float*)d_in[4];
    const float* out_proj_w= (const float*)d_in[5];
    const float* out_proj_b= (const float*)d_in[6];
    // d_in[7]=va_w, d_in[8]=va_b : unused (uniform softmaxes)
    const float* w_ih      = (const float*)d_in[9];
    const float* w_hh      = (const float*)d_in[10];
    const float* b_ih      = (const float*)d_in[11];
    const float* b_hh      = (const float*)d_in[12];
    const float* lin1_w    = (const float*)d_in[13];
    const float* lin1_b    = (const float*)d_in[14];
    const float* lin2_w    = (const float*)d_in[15];
    const float* lin2_b    = (const float*)d_in[16];
    float* out = (float*)d_out;

    float *pG, *pPk, *pF1, *pWbig, *pbatt, *pbihh, *pXT, *pLT, *pH1;
    cudaGetSymbolAddress((void**)&pG,    d_G);
    cudaGetSymbolAddress((void**)&pPk,   d_Pk);
    cudaGetSymbolAddress((void**)&pF1,   d_F1);
    cudaGetSymbolAddress((void**)&pWbig, d_Wbig);
    cudaGetSymbolAddress((void**)&pbatt, d_batt);
    cudaGetSymbolAddress((void**)&pbihh, d_bihh);
    cudaGetSymbolAddress((void**)&pXT,   d_XT);
    cudaGetSymbolAddress((void**)&pLT,   d_LT);
    cudaGetSymbolAddress((void**)&pH1,   d_H1);

    static int smem_set = 0;
    if (!smem_set) {
        cudaFuncSetAttribute(k_lstm, cudaFuncAttributeMaxDynamicSharedMemorySize,
                             SM_TOTAL);
        smem_set = 1;
    }

    const float* bv = in_proj_b + 2 * D_;
    const float* Wv = in_proj_w + (size_t)2 * D_ * D_;
    const int KQ = D_ / 4;

    k_init<<<ROWS, 256>>>(traj, gcn_w, gcn_b);

    k_gemv<<<32, 256>>>(out_proj_w, D_, bv, out_proj_b, nullptr, pbatt, D_);
    k_gemv<<<256, 256>>>(w_ih, D_, pbatt, b_ih, b_hh, pbihh, G4);

    // F1 = w_ih @ Wop   (fp32 split-K=4)
    sgemm_fold<<<dim3(D_ / 128, G4 / 64, 4), 256>>>(
        w_ih, out_proj_w, pPk, G4, D_, KQ, D_, D_,
        (size_t)KQ, (size_t)KQ * D_);
    k_addn<<<(G4 * D_ / 4 + 255) / 256, 256>>>(pPk, pF1, G4 * D_ / 4, 4);

    // Wbig = F1 @ Wv    (fp32 split-K=4)
    sgemm_fold<<<dim3(D_ / 128, G4 / 64, 4), 256>>>(
        pF1, Wv, pPk, G4, D_, KQ, D_, D_,
        (size_t)KQ, (size_t)KQ * D_);
    k_addn<<<(G4 * D_ / 4 + 255) / 256, 256>>>(pPk, pWbig, G4 * D_ / 4, 4);

    // XT = Wbig @ G^T + bias_x[m]   (tf32)
    tf32gemm<0, 0, 1, 0, 0><<<dim3(ROWS / 128, G4 / 128), 256>>>(
        pWbig, pG, pbihh, pXT, G4, ROWS, D_, D_, D_);

    // persistent LSTM (64 blocks)
    k_lstm<<<NBLK, 256, SM_TOTAL>>>(w_hh);

    // H1 = relu(L @ lin1_w^T + b)   (tf32, A = LT k-major)
    tf32gemm<1, 0, 2, 1, 0><<<dim3(D_ / 128, ROWS / 128), 256>>>(
        pLT, lin1_w, lin1_b, pH1, ROWS, D_, LH, ROWS, LH);

    // out = H1 @ lin2_w^T + b       (tf32, permuted rows)
    tf32gemm<0, 0, 2, 0, 1><<<dim3(128 / 128, ROWS / 128), 256>>>(
        pH1, lin2_w, lin2_b, out, ROWS, 128, D_, D_, D_);
}